// round 10
// baseline (speedup 1.0000x reference)
#include <cuda_runtime.h>
#include <math.h>

#define Bn 2
#define Cn 21
#define Hn 512
#define Wn 512
#define HL 128
#define WL 128
#define Kn 11
#define SPANn 5
#define KKn 121

#define PP 144
#define XOFF 5
#define YOFF 8
#define PLANE (PP*PP)

#define GK_TILE 128
#define GK_SMEM_BYTES (KKn * GK_TILE * 4)

__device__ float g_ppad [Bn*Cn*PLANE];
__device__ float g_msg  [Bn*Cn*HL*WL];
__device__ float g_cf   [Bn*3*HL*WL];
__device__ float g_gk   [Bn*16*8*KKn*GK_TILE];

__constant__ float c_wtab[4] = {0.375f, 0.125f, 0.875f, 0.625f};

// ---------------------------------------------------------------------------
__global__ void k_zero() {
    int idx = blockIdx.x * 256 + threadIdx.x;
    if (idx < Bn*Cn*PLANE/4) ((float4*)g_ppad)[idx] = make_float4(0.f,0.f,0.f,0.f);
}

// ---------------------------------------------------------------------------
__global__ void k_pool_img(const float* __restrict__ img, const float* __restrict__ schan) {
    int idx = blockIdx.x * 256 + threadIdx.x;
    if (idx >= Bn*3*HL*WL) return;
    int y = idx & (WL-1);
    int x = (idx >> 7) & (HL-1);
    int c = (idx >> 14) % 3;
    int b = idx / (3*HL*WL);
    const float* src = img + ((b*3 + c)*Hn + x*4)*Wn + y*4;
    float s = 0.f;
    #pragma unroll
    for (int i = 0; i < 4; i++)
        #pragma unroll
        for (int j = 0; j < 4; j++) s += src[i*Wn + j];
    g_cf[idx] = s * (schan[0] * 0.0625f);
}

// ---------------------------------------------------------------------------
// gauss kernel, tiled per 8x16 pixel block (exact R9)
__global__ void k_gauss(const float* __restrict__ pos_sdims,
                        const float* __restrict__ pos_compat,
                        const float* __restrict__ col_compat) {
    __shared__ float cf_s[3][18*26];
    __shared__ float pos_s[KKn];
    int tyi = blockIdx.x, txi = blockIdx.y, b = blockIdx.z;
    int t = threadIdx.x;
    int x0 = txi*8 - SPANn, y0 = tyi*16 - SPANn;
    if (t < KKn) {
        int i = t / 11, j = t - i*11;
        int dx = i - SPANn, dy = j - SPANn;
        float sd4 = 4.f * pos_sdims[0];
        float dpos2 = sd4*sd4 * (float)(dx*dx + dy*dy);
        pos_s[t] = pos_compat[0] * __expf(-0.5f*dpos2);
    }
    for (int i = t; i < 3*468; i += 128) {
        int c = i / 468, rem = i % 468;
        int xx = x0 + rem/26, yy = y0 + rem%26;
        float v = 0.f;
        if ((unsigned)xx < HL && (unsigned)yy < WL)
            v = g_cf[((b*3 + c)*HL + xx)*WL + yy];
        cf_s[c][rem] = v;
    }
    __syncthreads();
    int px = t >> 4, py = t & 15;
    int ctr = (px + SPANn)*26 + (py + SPANn);
    float c0 = cf_s[0][ctr], c1 = cf_s[1][ctr], c2 = cf_s[2][ctr];
    float cc = col_compat[0];
    int gx = txi*8 + px, gy = tyi*16 + py;
    float* outb = g_gk + (size_t)(((b*16 + txi)*8 + tyi)*KKn)*GK_TILE + t;
    #pragma unroll 1
    for (int ij = 0; ij < KKn; ij++) {
        int i = ij / 11, j = ij - i*11;
        int dx = i - SPANn, dy = j - SPANn;
        bool valid = ((unsigned)(gx + dx) < HL) && ((unsigned)(gy + dy) < WL);
        int si = (px + i)*26 + (py + j);
        float d0 = cf_s[0][si] - c0;
        float d1 = cf_s[1][si] - c1;
        float d2 = cf_s[2][si] - c2;
        float dcol2 = d0*d0 + d1*d1 + d2*d2;
        float gval = valid ? (pos_s[ij] + cc * __expf(-0.5f*dcol2)) : 0.f;
        outb[ij*GK_TILE] = gval;
    }
}

// ---------------------------------------------------------------------------
// 3) pooled init pred, float4 per thread. Warp: xr = l>>3 (4 X rows), yq = l&7.
__global__ __launch_bounds__(256) void k_init(const float* __restrict__ unary) {
    int b = blockIdx.z;
    int w = threadIdx.x >> 5, l = threadIdx.x & 31;
    int xr = l >> 3, yq = l & 7;
    int X  = blockIdx.y*32 + w*4 + xr;
    int Yb = blockIdx.x*32 + yq*4;
    const float4* up = (const float4*)(unary + ((size_t)(b*Cn)*Hn + X)*Wn + Yb);
    const size_t cs = (size_t)Hn*Wn/4;
    float4 u[Cn];
    #pragma unroll
    for (int c = 0; c < Cn; c++) u[c] = __ldg(up + c*cs);
    float4 m = u[0];
    #pragma unroll
    for (int c = 1; c < Cn; c++) {
        m.x = fmaxf(m.x, u[c].x); m.y = fmaxf(m.y, u[c].y);
        m.z = fmaxf(m.z, u[c].z); m.w = fmaxf(m.w, u[c].w);
    }
    float4 s = make_float4(0.f,0.f,0.f,0.f);
    #pragma unroll
    for (int c = 0; c < Cn; c++) {
        s.x += __expf(u[c].x - m.x); s.y += __expf(u[c].y - m.y);
        s.z += __expf(u[c].z - m.z); s.w += __expf(u[c].w - m.w);
    }
    float lsesum = (m.x + __logf(s.x)) + (m.y + __logf(s.y))
                 + (m.z + __logf(s.z)) + (m.w + __logf(s.w));
    int xp = blockIdx.y*8 + w + XOFF;
    int yp = blockIdx.x*8 + yq + YOFF;
    #pragma unroll
    for (int c = 0; c < Cn; c++) {
        float pc = (u[c].x + u[c].y + u[c].z + u[c].w) - lsesum;
        pc += __shfl_xor_sync(0xffffffffu, pc, 8);
        pc += __shfl_xor_sync(0xffffffffu, pc, 16);
        if (xr == 0)
            g_ppad[((size_t)(b*Cn + c)*PP + xp)*PP + yp] = pc * 0.0625f;
    }
}

// ---------------------------------------------------------------------------
// 4) message passing (exact R9)
__global__ __launch_bounds__(224) void k_msg() {
    extern __shared__ float gk_s[];
    const int t = threadIdx.x;
    const int b = blockIdx.z;
    const int tyi = blockIdx.x, txi = blockIdx.y;
    const int chunk = t >> 5, lane = t & 31;
    const int xrow = lane >> 2, yg = lane & 3;
    const int pxg = txi*8 + xrow;
    const int Yb  = tyi*16 + yg*4;
    const float* gbase = g_gk + (size_t)(((b*16 + txi)*8 + tyi)*KKn)*GK_TILE;

    {
        const float4* src = (const float4*)gbase;
        #pragma unroll 4
        for (int idx = t; idx < KKn*32; idx += 224) {
            ((float4*)gk_s)[idx] = __ldg(src + idx);
        }
    }
    __syncthreads();

    float acc[3][4];
    #pragma unroll
    for (int c = 0; c < 3; c++)
        #pragma unroll
        for (int k = 0; k < 4; k++) acc[c][k] = 0.f;

    const int pix = lane*4;
    #pragma unroll 1
    for (int i = 0; i < 11; i++) {
        float pr[3][20];
        #pragma unroll
        for (int c = 0; c < 3; c++) {
            const float4* pp = (const float4*)(g_ppad +
                ((size_t)(b*Cn + chunk*3 + c)*PP + (pxg + i))*PP + Yb);
            #pragma unroll
            for (int q = 0; q < 5; q++) {
                float4 v = __ldg(pp + q);
                pr[c][q*4+0] = v.x; pr[c][q*4+1] = v.y;
                pr[c][q*4+2] = v.z; pr[c][q*4+3] = v.w;
            }
        }
        const float* gs = gk_s + i*11*GK_TILE + pix;
        #pragma unroll
        for (int j = 0; j < 11; j++) {
            float4 gv = *(const float4*)(gs + j*GK_TILE);
            #pragma unroll
            for (int c = 0; c < 3; c++) {
                acc[c][0] += gv.x * pr[c][0 + j + 3];
                acc[c][1] += gv.y * pr[c][1 + j + 3];
                acc[c][2] += gv.z * pr[c][2 + j + 3];
                acc[c][3] += gv.w * pr[c][3 + j + 3];
            }
        }
    }

    #pragma unroll
    for (int c = 0; c < 3; c++) {
        float* mp = g_msg + ((size_t)(b*Cn + chunk*3 + c)*HL + pxg)*WL + Yb;
        *(float4*)mp = make_float4(acc[c][0], acc[c][1], acc[c][2], acc[c][3]);
    }
}

// ---------------------------------------------------------------------------
// 5) fused iter, float4 per thread
__global__ __launch_bounds__(256) void k_iter(const float* __restrict__ unary,
                                              const float* __restrict__ weight) {
    __shared__ float m_s[Cn*100];   // [c][10 x][10 y]
    int b = blockIdx.z;
    int t = threadIdx.x, w = t >> 5, l = t & 31;
    int lx0 = blockIdx.y*8 - 1, ly0 = blockIdx.x*8 - 1;
    for (int i = t; i < Cn*100; i += 256) {
        int c = i / 100, rem = i % 100;
        int xx = lx0 + rem/10; xx = max(0, min(HL-1, xx));
        int yy = ly0 + rem%10; yy = max(0, min(WL-1, yy));
        m_s[i] = g_msg[((b*Cn + c)*HL + xx)*WL + yy];
    }
    __syncthreads();
    int xr = l >> 3, yq = l & 7;
    int X  = blockIdx.y*32 + w*4 + xr;
    int Yb = blockIdx.x*32 + yq*4;
    const float4* up = (const float4*)(unary + ((size_t)(b*Cn)*Hn + X)*Wn + Yb);
    const size_t cs = (size_t)Hn*Wn/4;
    float wgt = weight[0], uw = 1.f - wgt;
    float wx0 = c_wtab[xr], wx1 = 1.f - wx0;
    int xA = w + 1 + ((xr < 2) ? -1 : 0);
    float4 u[Cn];
    float4 mx = make_float4(-1e30f,-1e30f,-1e30f,-1e30f);
    #pragma unroll
    for (int c = 0; c < Cn; c++) {
        float4 uv = __ldg(up + c*cs);
        const float* mc = m_s + c*100 + xA*10 + yq;
        float a0 = mc[0],  a1 = mc[1],  a2 = mc[2];
        float b0 = mc[10], b1 = mc[11], b2 = mc[12];
        float r0 = wx0*a0 + wx1*b0;
        float r1 = wx0*a1 + wx1*b1;
        float r2 = wx0*a2 + wx1*b2;
        float4 v;
        v.x = uw*uv.x + wgt*(0.375f*r0 + 0.625f*r1);
        v.y = uw*uv.y + wgt*(0.125f*r0 + 0.875f*r1);
        v.z = uw*uv.z + wgt*(0.875f*r1 + 0.125f*r2);
        v.w = uw*uv.w + wgt*(0.625f*r1 + 0.375f*r2);
        u[c] = v;
        mx.x = fmaxf(mx.x, v.x); mx.y = fmaxf(mx.y, v.y);
        mx.z = fmaxf(mx.z, v.z); mx.w = fmaxf(mx.w, v.w);
    }
    float4 s = make_float4(0.f,0.f,0.f,0.f);
    #pragma unroll
    for (int c = 0; c < Cn; c++) {
        u[c].x = __expf(u[c].x - mx.x); s.x += u[c].x;
        u[c].y = __expf(u[c].y - mx.y); s.y += u[c].y;
        u[c].z = __expf(u[c].z - mx.z); s.z += u[c].z;
        u[c].w = __expf(u[c].w - mx.w); s.w += u[c].w;
    }
    float ix = 1.f/s.x, iy = 1.f/s.y, iz = 1.f/s.z, iwv = 1.f/s.w;
    int xp = blockIdx.y*8 + w + XOFF;
    int yp = blockIdx.x*8 + yq + YOFF;
    #pragma unroll
    for (int c = 0; c < Cn; c++) {
        float pc = u[c].x*ix + u[c].y*iy + u[c].z*iz + u[c].w*iwv;
        pc += __shfl_xor_sync(0xffffffffu, pc, 8);
        pc += __shfl_xor_sync(0xffffffffu, pc, 16);
        if (xr == 0)
            g_ppad[((size_t)(b*Cn + c)*PP + xp)*PP + yp] = pc * 0.0625f;
    }
}

// ---------------------------------------------------------------------------
// 6) final, float4 per thread, STG.128 output
__global__ __launch_bounds__(256) void k_final(const float* __restrict__ unary,
                                               const float* __restrict__ weight,
                                               float* __restrict__ out) {
    __shared__ float m_s[Cn*100];
    int b = blockIdx.z;
    int t = threadIdx.x, w = t >> 5, l = t & 31;
    int lx0 = blockIdx.y*8 - 1, ly0 = blockIdx.x*8 - 1;
    for (int i = t; i < Cn*100; i += 256) {
        int c = i / 100, rem = i % 100;
        int xx = lx0 + rem/10; xx = max(0, min(HL-1, xx));
        int yy = ly0 + rem%10; yy = max(0, min(WL-1, yy));
        m_s[i] = g_msg[((b*Cn + c)*HL + xx)*WL + yy];
    }
    __syncthreads();
    int xr = l >> 3, yq = l & 7;
    int X  = blockIdx.y*32 + w*4 + xr;
    int Yb = blockIdx.x*32 + yq*4;
    const float4* up = (const float4*)(unary + ((size_t)(b*Cn)*Hn + X)*Wn + Yb);
    float4* op = (float4*)(out + ((size_t)(b*Cn)*Hn + X)*Wn + Yb);
    const size_t cs = (size_t)Hn*Wn/4;
    float wgt = weight[0], uw = 1.f - wgt;
    float wx0 = c_wtab[xr], wx1 = 1.f - wx0;
    int xA = w + 1 + ((xr < 2) ? -1 : 0);
    float4 u[Cn];
    float4 mx;
    #pragma unroll
    for (int c = 0; c < Cn; c++) {
        u[c] = __ldg(up + c*cs);
        if (c == 0) mx = u[0];
        else {
            mx.x = fmaxf(mx.x, u[c].x); mx.y = fmaxf(mx.y, u[c].y);
            mx.z = fmaxf(mx.z, u[c].z); mx.w = fmaxf(mx.w, u[c].w);
        }
    }
    float4 s = make_float4(0.f,0.f,0.f,0.f);
    #pragma unroll
    for (int c = 0; c < Cn; c++) {
        s.x += __expf(u[c].x - mx.x); s.y += __expf(u[c].y - mx.y);
        s.z += __expf(u[c].z - mx.z); s.w += __expf(u[c].w - mx.w);
    }
    float4 lse;
    lse.x = mx.x + __logf(s.x); lse.y = mx.y + __logf(s.y);
    lse.z = mx.z + __logf(s.z); lse.w = mx.w + __logf(s.w);
    #pragma unroll
    for (int c = 0; c < Cn; c++) {
        const float* mc = m_s + c*100 + xA*10 + yq;
        float a0 = mc[0],  a1 = mc[1],  a2 = mc[2];
        float b0 = mc[10], b1 = mc[11], b2 = mc[12];
        float r0 = wx0*a0 + wx1*b0;
        float r1 = wx0*a1 + wx1*b1;
        float r2 = wx0*a2 + wx1*b2;
        float4 o;
        o.x = uw*(u[c].x - lse.x) + wgt*(0.375f*r0 + 0.625f*r1);
        o.y = uw*(u[c].y - lse.y) + wgt*(0.125f*r0 + 0.875f*r1);
        o.z = uw*(u[c].z - lse.z) + wgt*(0.875f*r1 + 0.125f*r2);
        o.w = uw*(u[c].w - lse.w) + wgt*(0.625f*r1 + 0.375f*r2);
        op[c*cs] = o;
    }
}

// ---------------------------------------------------------------------------
extern "C" void kernel_launch(void* const* d_in, const int* in_sizes, int n_in,
                              void* d_out, int out_size) {
    const float* unary      = (const float*)d_in[0];
    const float* img        = (const float*)d_in[1];
    const float* pos_sdims  = (const float*)d_in[2];
    const float* col_schan  = (const float*)d_in[3];
    const float* pos_compat = (const float*)d_in[4];
    const float* col_compat = (const float*)d_in[5];
    const float* weight     = (const float*)d_in[6];
    float* out = (float*)d_out;

    static int smem_set = 0;
    if (!smem_set) {
        cudaFuncSetAttribute(k_msg, cudaFuncAttributeMaxDynamicSharedMemorySize,
                             GK_SMEM_BYTES);
        smem_set = 1;
    }

    k_zero<<<(Bn*Cn*PLANE/4 + 255)/256, 256>>>();
    k_pool_img<<<(Bn*3*HL*WL + 255)/256, 256>>>(img, col_schan);
    k_gauss<<<dim3(8, 16, Bn), 128>>>(pos_sdims, pos_compat, col_compat);
    k_init<<<dim3(16, 16, Bn), 256>>>(unary);
    for (int it = 0; it < 5; it++) {
        k_msg<<<dim3(8, 16, Bn), 224, GK_SMEM_BYTES>>>();
        if (it < 4)
            k_iter<<<dim3(16, 16, Bn), 256>>>(unary, weight);
        else
            k_final<<<dim3(16, 16, Bn), 256>>>(unary, weight, out);
    }
}

// round 11
// speedup vs baseline: 1.1819x; 1.1819x over previous
#include <cuda_runtime.h>
#include <math.h>

#define Bn 2
#define Cn 21
#define Hn 512
#define Wn 512
#define HL 128
#define WL 128
#define Kn 11
#define SPANn 5
#define KKn 121

#define PP 144
#define XOFF 5
#define YOFF 8
#define PLANE (PP*PP)

#define GK_TILE 128
#define GK_SMEM_BYTES (KKn * GK_TILE * 4)

__device__ float g_ppad [Bn*Cn*PLANE];
__device__ float g_msg  [Bn*Cn*HL*WL];
__device__ float g_cf   [Bn*3*HL*WL];
__device__ float g_gk   [Bn*16*8*KKn*GK_TILE];

__constant__ float c_wtab[4] = {0.375f, 0.125f, 0.875f, 0.625f};

// ---------------------------------------------------------------------------
__global__ void k_zero() {
    int idx = blockIdx.x * 256 + threadIdx.x;
    if (idx < Bn*Cn*PLANE/4) ((float4*)g_ppad)[idx] = make_float4(0.f,0.f,0.f,0.f);
}

// ---------------------------------------------------------------------------
__global__ void k_pool_img(const float* __restrict__ img, const float* __restrict__ schan) {
    int idx = blockIdx.x * 256 + threadIdx.x;
    if (idx >= Bn*3*HL*WL) return;
    int y = idx & (WL-1);
    int x = (idx >> 7) & (HL-1);
    int c = (idx >> 14) % 3;
    int b = idx / (3*HL*WL);
    const float* src = img + ((b*3 + c)*Hn + x*4)*Wn + y*4;
    float s = 0.f;
    #pragma unroll
    for (int i = 0; i < 4; i++)
        #pragma unroll
        for (int j = 0; j < 4; j++) s += src[i*Wn + j];
    g_cf[idx] = s * (schan[0] * 0.0625f);
}

// ---------------------------------------------------------------------------
// gauss kernel, tiled per 8x16 pixel block (exact R9)
__global__ void k_gauss(const float* __restrict__ pos_sdims,
                        const float* __restrict__ pos_compat,
                        const float* __restrict__ col_compat) {
    __shared__ float cf_s[3][18*26];
    __shared__ float pos_s[KKn];
    int tyi = blockIdx.x, txi = blockIdx.y, b = blockIdx.z;
    int t = threadIdx.x;
    int x0 = txi*8 - SPANn, y0 = tyi*16 - SPANn;
    if (t < KKn) {
        int i = t / 11, j = t - i*11;
        int dx = i - SPANn, dy = j - SPANn;
        float sd4 = 4.f * pos_sdims[0];
        float dpos2 = sd4*sd4 * (float)(dx*dx + dy*dy);
        pos_s[t] = pos_compat[0] * __expf(-0.5f*dpos2);
    }
    for (int i = t; i < 3*468; i += 128) {
        int c = i / 468, rem = i % 468;
        int xx = x0 + rem/26, yy = y0 + rem%26;
        float v = 0.f;
        if ((unsigned)xx < HL && (unsigned)yy < WL)
            v = g_cf[((b*3 + c)*HL + xx)*WL + yy];
        cf_s[c][rem] = v;
    }
    __syncthreads();
    int px = t >> 4, py = t & 15;
    int ctr = (px + SPANn)*26 + (py + SPANn);
    float c0 = cf_s[0][ctr], c1 = cf_s[1][ctr], c2 = cf_s[2][ctr];
    float cc = col_compat[0];
    int gx = txi*8 + px, gy = tyi*16 + py;
    float* outb = g_gk + (size_t)(((b*16 + txi)*8 + tyi)*KKn)*GK_TILE + t;
    #pragma unroll 1
    for (int ij = 0; ij < KKn; ij++) {
        int i = ij / 11, j = ij - i*11;
        int dx = i - SPANn, dy = j - SPANn;
        bool valid = ((unsigned)(gx + dx) < HL) && ((unsigned)(gy + dy) < WL);
        int si = (px + i)*26 + (py + j);
        float d0 = cf_s[0][si] - c0;
        float d1 = cf_s[1][si] - c1;
        float d2 = cf_s[2][si] - c2;
        float dcol2 = d0*d0 + d1*d1 + d2*d2;
        float gval = valid ? (pos_s[ij] + cc * __expf(-0.5f*dcol2)) : 0.f;
        outb[ij*GK_TILE] = gval;
    }
}

// ---------------------------------------------------------------------------
// 3) pooled init pred, ONE row per thread. Block 256 = 8 warps = 8 X rows x 32 Y.
//    Tile 8X x 32Y, grid (16, 64, Bn) = 2048 blocks.
__global__ __launch_bounds__(256) void k_init(const float* __restrict__ unary) {
    __shared__ float part[8*8*Cn];       // [w][yq][c]
    int b = blockIdx.z;
    int w = threadIdx.x >> 5, l = threadIdx.x & 31;
    int X = blockIdx.y*8 + w;
    int Y = blockIdx.x*32 + l;
    const float* up = unary + ((size_t)(b*Cn)*Hn + X)*Wn + Y;
    float u[Cn];
    float m = -1e30f;
    #pragma unroll
    for (int c = 0; c < Cn; c++) {
        u[c] = __ldg(up + (size_t)c*Hn*Wn);
        m = fmaxf(m, u[c]);
    }
    float s = 0.f;
    #pragma unroll
    for (int c = 0; c < Cn; c++) s += __expf(u[c] - m);
    float lse = m + __logf(s);
    int yq = l >> 2;
    #pragma unroll
    for (int c = 0; c < Cn; c++) {
        float r = u[c] - lse;
        r += __shfl_xor_sync(0xffffffffu, r, 1);
        r += __shfl_xor_sync(0xffffffffu, r, 2);
        if ((l & 3) == 0) part[(w*8 + yq)*Cn + c] = r;
    }
    __syncthreads();
    for (int idx = threadIdx.x; idx < 2*8*Cn; idx += 256) {
        int c = idx % Cn, rem = idx / Cn;
        int q = rem & 7, xc = rem >> 3;
        float ss = part[((xc*4+0)*8 + q)*Cn + c] + part[((xc*4+1)*8 + q)*Cn + c]
                 + part[((xc*4+2)*8 + q)*Cn + c] + part[((xc*4+3)*8 + q)*Cn + c];
        g_ppad[((size_t)(b*Cn + c)*PP + blockIdx.y*2 + xc + XOFF)*PP
               + blockIdx.x*8 + q + YOFF] = ss * 0.0625f;
    }
}

// ---------------------------------------------------------------------------
// 4) message passing (exact R9)
__global__ __launch_bounds__(224) void k_msg() {
    extern __shared__ float gk_s[];
    const int t = threadIdx.x;
    const int b = blockIdx.z;
    const int tyi = blockIdx.x, txi = blockIdx.y;
    const int chunk = t >> 5, lane = t & 31;
    const int xrow = lane >> 2, yg = lane & 3;
    const int pxg = txi*8 + xrow;
    const int Yb  = tyi*16 + yg*4;
    const float* gbase = g_gk + (size_t)(((b*16 + txi)*8 + tyi)*KKn)*GK_TILE;

    {
        const float4* src = (const float4*)gbase;
        #pragma unroll 4
        for (int idx = t; idx < KKn*32; idx += 224) {
            ((float4*)gk_s)[idx] = __ldg(src + idx);
        }
    }
    __syncthreads();

    float acc[3][4];
    #pragma unroll
    for (int c = 0; c < 3; c++)
        #pragma unroll
        for (int k = 0; k < 4; k++) acc[c][k] = 0.f;

    const int pix = lane*4;
    #pragma unroll 1
    for (int i = 0; i < 11; i++) {
        float pr[3][20];
        #pragma unroll
        for (int c = 0; c < 3; c++) {
            const float4* pp = (const float4*)(g_ppad +
                ((size_t)(b*Cn + chunk*3 + c)*PP + (pxg + i))*PP + Yb);
            #pragma unroll
            for (int q = 0; q < 5; q++) {
                float4 v = __ldg(pp + q);
                pr[c][q*4+0] = v.x; pr[c][q*4+1] = v.y;
                pr[c][q*4+2] = v.z; pr[c][q*4+3] = v.w;
            }
        }
        const float* gs = gk_s + i*11*GK_TILE + pix;
        #pragma unroll
        for (int j = 0; j < 11; j++) {
            float4 gv = *(const float4*)(gs + j*GK_TILE);
            #pragma unroll
            for (int c = 0; c < 3; c++) {
                acc[c][0] += gv.x * pr[c][0 + j + 3];
                acc[c][1] += gv.y * pr[c][1 + j + 3];
                acc[c][2] += gv.z * pr[c][2 + j + 3];
                acc[c][3] += gv.w * pr[c][3 + j + 3];
            }
        }
    }

    #pragma unroll
    for (int c = 0; c < 3; c++) {
        float* mp = g_msg + ((size_t)(b*Cn + chunk*3 + c)*HL + pxg)*WL + Yb;
        *(float4*)mp = make_float4(acc[c][0], acc[c][1], acc[c][2], acc[c][3]);
    }
}

// ---------------------------------------------------------------------------
// 5) fused iter, ONE row per thread. Tile 8X x 32Y, grid (16, 64, Bn).
__global__ __launch_bounds__(256) void k_iter(const float* __restrict__ unary,
                                              const float* __restrict__ weight) {
    __shared__ float m_s[Cn*40];         // [c][4 x][10 y]
    __shared__ float part[8*8*Cn];
    int b = blockIdx.z;
    int t = threadIdx.x, w = t >> 5, l = t & 31;
    int lx0 = blockIdx.y*2 - 1, ly0 = blockIdx.x*8 - 1;
    for (int i = t; i < Cn*40; i += 256) {
        int c = i / 40, rem = i % 40;
        int xx = lx0 + rem/10; xx = max(0, min(HL-1, xx));
        int yy = ly0 + rem%10; yy = max(0, min(WL-1, yy));
        m_s[i] = g_msg[((b*Cn + c)*HL + xx)*WL + yy];
    }
    __syncthreads();
    int X = blockIdx.y*8 + w;
    int Y = blockIdx.x*32 + l;
    const float* up = unary + ((size_t)(b*Cn)*Hn + X)*Wn + Y;
    float wgt = weight[0], uw = 1.f - wgt;
    int rx = w & 3, ry = l & 3;
    float wx0 = c_wtab[rx], wx1 = 1.f - wx0;
    float wy0 = c_wtab[ry], wy1 = 1.f - wy0;
    int xA = (w >> 2) + 1 + ((rx < 2) ? -1 : 0);
    int yA = (l >> 2) + 1 + ((ry < 2) ? -1 : 0);
    int base = xA*10 + yA;
    float v[Cn];
    float mmax = -1e30f;
    #pragma unroll
    for (int c = 0; c < Cn; c++) {
        const float* mc = m_s + c*40 + base;
        float mu = wx0*(wy0*mc[0] + wy1*mc[1]) + wx1*(wy0*mc[10] + wy1*mc[11]);
        float vv = uw * __ldg(up + (size_t)c*Hn*Wn) + wgt * mu;
        v[c] = vv;
        mmax = fmaxf(mmax, vv);
    }
    float s = 0.f;
    #pragma unroll
    for (int c = 0; c < Cn; c++) { v[c] = __expf(v[c] - mmax); s += v[c]; }
    float inv = 1.f / s;
    int yq = l >> 2;
    #pragma unroll
    for (int c = 0; c < Cn; c++) {
        float r = v[c] * inv;
        r += __shfl_xor_sync(0xffffffffu, r, 1);
        r += __shfl_xor_sync(0xffffffffu, r, 2);
        if ((l & 3) == 0) part[(w*8 + yq)*Cn + c] = r;
    }
    __syncthreads();
    for (int idx = t; idx < 2*8*Cn; idx += 256) {
        int c = idx % Cn, rem = idx / Cn;
        int q = rem & 7, xc = rem >> 3;
        float ss = part[((xc*4+0)*8 + q)*Cn + c] + part[((xc*4+1)*8 + q)*Cn + c]
                 + part[((xc*4+2)*8 + q)*Cn + c] + part[((xc*4+3)*8 + q)*Cn + c];
        g_ppad[((size_t)(b*Cn + c)*PP + blockIdx.y*2 + xc + XOFF)*PP
               + blockIdx.x*8 + q + YOFF] = ss * 0.0625f;
    }
}

// ---------------------------------------------------------------------------
// 6) final, ONE row per thread. No pooling.
__global__ __launch_bounds__(256) void k_final(const float* __restrict__ unary,
                                               const float* __restrict__ weight,
                                               float* __restrict__ out) {
    __shared__ float m_s[Cn*40];
    int b = blockIdx.z;
    int t = threadIdx.x, w = t >> 5, l = t & 31;
    int lx0 = blockIdx.y*2 - 1, ly0 = blockIdx.x*8 - 1;
    for (int i = t; i < Cn*40; i += 256) {
        int c = i / 40, rem = i % 40;
        int xx = lx0 + rem/10; xx = max(0, min(HL-1, xx));
        int yy = ly0 + rem%10; yy = max(0, min(WL-1, yy));
        m_s[i] = g_msg[((b*Cn + c)*HL + xx)*WL + yy];
    }
    __syncthreads();
    int X = blockIdx.y*8 + w;
    int Y = blockIdx.x*32 + l;
    const float* up   = unary + ((size_t)(b*Cn)*Hn + X)*Wn + Y;
    float*       outp = out   + ((size_t)(b*Cn)*Hn + X)*Wn + Y;
    float wgt = weight[0], uw = 1.f - wgt;
    int rx = w & 3, ry = l & 3;
    float wx0 = c_wtab[rx], wx1 = 1.f - wx0;
    float wy0 = c_wtab[ry], wy1 = 1.f - wy0;
    int xA = (w >> 2) + 1 + ((rx < 2) ? -1 : 0);
    int yA = (l >> 2) + 1 + ((ry < 2) ? -1 : 0);
    int base = xA*10 + yA;
    float u[Cn];
    float m = -1e30f;
    #pragma unroll
    for (int c = 0; c < Cn; c++) {
        u[c] = __ldg(up + (size_t)c*Hn*Wn);
        m = fmaxf(m, u[c]);
    }
    float s = 0.f;
    #pragma unroll
    for (int c = 0; c < Cn; c++) s += __expf(u[c] - m);
    float lse = m + __logf(s);
    #pragma unroll
    for (int c = 0; c < Cn; c++) {
        const float* mc = m_s + c*40 + base;
        float mu = wx0*(wy0*mc[0] + wy1*mc[1]) + wx1*(wy0*mc[10] + wy1*mc[11]);
        outp[(size_t)c*Hn*Wn] = uw * (u[c] - lse) + wgt * mu;
    }
}

// ---------------------------------------------------------------------------
extern "C" void kernel_launch(void* const* d_in, const int* in_sizes, int n_in,
                              void* d_out, int out_size) {
    const float* unary      = (const float*)d_in[0];
    const float* img        = (const float*)d_in[1];
    const float* pos_sdims  = (const float*)d_in[2];
    const float* col_schan  = (const float*)d_in[3];
    const float* pos_compat = (const float*)d_in[4];
    const float* col_compat = (const float*)d_in[5];
    const float* weight     = (const float*)d_in[6];
    float* out = (float*)d_out;

    static int smem_set = 0;
    if (!smem_set) {
        cudaFuncSetAttribute(k_msg, cudaFuncAttributeMaxDynamicSharedMemorySize,
                             GK_SMEM_BYTES);
        smem_set = 1;
    }

    k_zero<<<(Bn*Cn*PLANE/4 + 255)/256, 256>>>();
    k_pool_img<<<(Bn*3*HL*WL + 255)/256, 256>>>(img, col_schan);
    k_gauss<<<dim3(8, 16, Bn), 128>>>(pos_sdims, pos_compat, col_compat);
    k_init<<<dim3(16, 64, Bn), 256>>>(unary);
    for (int it = 0; it < 5; it++) {
        k_msg<<<dim3(8, 16, Bn), 224, GK_SMEM_BYTES>>>();
        if (it < 4)
            k_iter<<<dim3(16, 64, Bn), 256>>>(unary, weight);
        else
            k_final<<<dim3(16, 64, Bn), 256>>>(unary, weight, out);
    }
}